// round 6
// baseline (speedup 1.0000x reference)
#include <cuda_runtime.h>
#include <math.h>

#define NC 1000
#define NA 64

// Scratch for pp = rowsum(W * P). __device__ global (no allocation allowed).
__device__ float g_pp[1024];

// Kernel 1: pp[row] = sum_k W[row,k] * P[row,k].  One warp per row, float2 per
// lane, fixed-order shuffle tree => deterministic. 125 blocks -> full-chip BW.
__global__ void pp_kernel(const float* __restrict__ W, const float* __restrict__ P) {
    int warp = (blockIdx.x * blockDim.x + threadIdx.x) >> 5;
    int lane = threadIdx.x & 31;
    if (warp >= NC) return;
    const float2* w2 = reinterpret_cast<const float2*>(W + warp * NA);
    const float2* p2 = reinterpret_cast<const float2*>(P + warp * NA);
    float2 w = w2[lane];
    float2 p = p2[lane];
    float s = w.x * p.x + w.y * p.y;
    #pragma unroll
    for (int off = 16; off; off >>= 1)
        s += __shfl_down_sync(0xffffffffu, s, off);
    if (lane == 0) g_pp[warp] = s;
}

// Kernel 2: closed-form solver.
//   q = softmax(pp); c = argmax(p0).
//   Beat condition per class is LINEAR in omega => single real crossover
//   theta_j = A/(A-B).  istar = first i with omega_i <= theta* = min_j theta_j.
//   Analytic index estimate, then an EXACT reference-loop walk (match first,
//   underflow cap, exact float recurrence/blends) from i_est-2 settles the
//   precise stop step.  The walk alone is a correct (slow) fallback.
__global__ __launch_bounds__(1024) void solve_kernel(const float* __restrict__ p0,
                                                     const float* __restrict__ omega,
                                                     float* __restrict__ out) {
    __shared__ float red_a[32], red_b[32], red_c[32];
    __shared__ int   red_i[32];
    __shared__ float s_maxpp, s_sumexp, s_p0c, s_ppc, s_theta;
    __shared__ int   s_c, s_done;
    __shared__ float s_cur;

    const unsigned FULL = 0xffffffffu;
    int tid  = threadIdx.x;
    int lane = tid & 31;
    int wid  = tid >> 5;
    bool live = (tid < NC);

    float w0 = omega[0];
    w0 = fminf(fmaxf(w0, 0.0f), 1.0f);

    float p0v = live ? p0[tid]   : -INFINITY;
    float ppv = live ? g_pp[tid] : -INFINITY;

    // ---- Phase A: max(pp)  +  argmax(p0) carrying pp[c] (one sync pair) ----
    {
        float m  = ppv;
        float av = p0v;
        int   ai = tid;
        float aw = ppv;
        #pragma unroll
        for (int off = 16; off; off >>= 1) {
            m = fmaxf(m, __shfl_down_sync(FULL, m, off));
            float ov = __shfl_down_sync(FULL, av, off);
            int   oi = __shfl_down_sync(FULL, ai, off);
            float ow = __shfl_down_sync(FULL, aw, off);
            if (ov > av || (ov == av && oi < ai)) { av = ov; ai = oi; aw = ow; }
        }
        if (lane == 0) { red_a[wid] = m; red_b[wid] = av; red_i[wid] = ai; red_c[wid] = aw; }
        __syncthreads();
        if (wid == 0) {
            float x  = red_a[lane];
            float bv = red_b[lane];
            int   bi = red_i[lane];
            float bw = red_c[lane];
            #pragma unroll
            for (int off = 16; off; off >>= 1) {
                x = fmaxf(x, __shfl_down_sync(FULL, x, off));
                float ov = __shfl_down_sync(FULL, bv, off);
                int   oi = __shfl_down_sync(FULL, bi, off);
                float ow = __shfl_down_sync(FULL, bw, off);
                if (ov > bv || (ov == bv && oi < bi)) { bv = ov; bi = oi; bw = ow; }
            }
            if (lane == 0) { s_maxpp = x; s_c = bi; s_p0c = bv; s_ppc = bw; }
        }
        __syncthreads();
    }

    // ---- Phase B: sum(exp(pp - max)) ----
    float e = live ? expf(ppv - s_maxpp) : 0.0f;
    {
        float s = e;
        #pragma unroll
        for (int off = 16; off; off >>= 1)
            s += __shfl_down_sync(FULL, s, off);
        if (lane == 0) red_a[wid] = s;
        __syncthreads();
        if (wid == 0) {
            float x = red_a[lane];
            #pragma unroll
            for (int off = 16; off; off >>= 1)
                x += __shfl_down_sync(FULL, x, off);
            if (lane == 0) s_sumexp = x;
        }
        __syncthreads();
    }
    float qv  = e / s_sumexp;
    int   c   = s_c;
    float p0c = s_p0c;
    float qc  = expf(s_ppc - s_maxpp) / s_sumexp;

    // ---- Phase C: theta* = min_j crossover(j) (analytic, real arithmetic) ----
    // j>c: beats iff d<0  -> crossover only if B<0.
    // j<c: beats iff d<=0 -> crossover if B<=0 (B==0 => theta=1, strict edge
    //      settled by the exact walk).
    float theta = INFINITY;
    if (live && tid != c) {
        float A = p0c - p0v;            // >= 0; > 0 for j < c
        float B = qc  - qv;
        bool cross = (tid < c) ? (B <= 0.0f) : (B < 0.0f);
        if (cross) theta = A / (A - B); // A-B > 0 whenever cross
    }
    {
        float m = theta;
        #pragma unroll
        for (int off = 16; off; off >>= 1)
            m = fminf(m, __shfl_down_sync(FULL, m, off));
        if (lane == 0) red_a[wid] = m;
        __syncthreads();
        if (wid == 0) {
            float x = red_a[lane];
            #pragma unroll
            for (int off = 16; off; off >>= 1)
                x = fminf(x, __shfl_down_sync(FULL, x, off));
            if (lane == 0) s_theta = x;
        }
        __syncthreads();
    }

    // ---- Analytic start index, exact omega recurrence to reach it ----
    if (tid == 0) {
        float th = s_theta;
        int i_start = 0;
        if (isfinite(th) && th < w0) {
            float f = (w0 - th) * 100.0f;          // / 0.01
            int ie = (int)ceilf(f);
            i_start = ie - 2;
            if (i_start < 0) i_start = 0;
            if (i_start > 150) i_start = 150;       // sequence length <= 101
        }
        float cur = w0;
        int k = 0;
        while (k < i_start) {                       // exact float recurrence
            float dec = cur - 0.01f;
            if (dec < 0.001f) break;                // underflow cap
            cur = dec;
            ++k;
        }
        s_cur  = cur;
        s_done = 0;
    }
    __syncthreads();

    // ---- Exact reference-loop walk from i_start (match first, then underflow) ----
    // Steps < i_start are guaranteed violating (real margin >> float band).
    for (int it = 0; it < 256; ++it) {
        float cur  = s_cur;
        float onem = 1.0f - cur;
        float vc = onem * p0c + cur * qc;
        float vj = onem * p0v + cur * qv;
        int viol = (live && tid != c) &&
                   ((tid < c) ? (vj >= vc) : (vj > vc));
        int any = __syncthreads_or(viol);
        if (tid == 0) {
            if (!any) s_done = 1;                   // argmax == c : stop, keep cur
            else {
                float dec = cur - 0.01f;
                if (dec < 0.001f) s_done = 1;       // underflow : stop, keep cur
                else s_cur = dec;
            }
        }
        __syncthreads();
        if (s_done) break;
    }

    // ---- Output: p = (1-omega*) * p0 + omega* * q, shape (1, NC) ----
    if (live) {
        float om = s_cur;
        out[tid] = (1.0f - om) * p0v + om * qv;
    }
}

extern "C" void kernel_launch(void* const* d_in, const int* in_sizes, int n_in,
                              void* d_out, int out_size) {
    const float* p0 = (const float*)d_in[0];
    const float* P  = (const float*)d_in[1];
    const float* W  = (const float*)d_in[2];
    const float* om = (const float*)d_in[3];
    float* out = (float*)d_out;

    pp_kernel<<<125, 256>>>(W, P);
    solve_kernel<<<1, 1024>>>(p0, om, out);
}